// round 2
// baseline (speedup 1.0000x reference)
#include <cuda_runtime.h>
#include <cuda_bf16.h>

// Problem constants
#define BB 8
#define TT 20
#define CIN 64
#define HID 64
#define HH 64
#define WW 64
#define HWSZ 4096          // 64*64
#define CC 128             // CIN + HID
#define C4 256             // 4*HID
#define EPSBN 1e-5f

typedef unsigned long long ull;

// -------- persistent device state (allocation-free scratch) --------
__device__ float g_h[BB * HID * HWSZ];        // hidden state   (8.4 MB)
__device__ float g_c[BB * HID * HWSZ];        // cell state     (8.4 MB)
__device__ float g_dws[BB * CC * HWSZ];       // selu(bn1(dwconv(z)))  (16.8 MB)
__device__ float g_wp[128 * 256];             // folded pw weights, layout [k][j][gate]
__device__ float g_sp[256];                   // folded bn2 shift, layout [j][gate]
__device__ float g_dwf[CC * 9];               // folded dw weights
__device__ float g_dwb[CC];                   // folded bn1 shift

// -------- helpers --------
__device__ __forceinline__ ull pack2(float a, float b) {
    ull r;
    asm("mov.b64 %0, {%1,%2};" : "=l"(r) : "f"(a), "f"(b));
    return r;
}
__device__ __forceinline__ ull fma2(ull a, ull b, ull c) {
    ull d;
    asm("fma.rn.f32x2 %0, %1, %2, %3;" : "=l"(d) : "l"(a), "l"(b), "l"(c));
    return d;
}
__device__ __forceinline__ float unpk(ull v, int hi) {
    float lo, h;
    asm("mov.b64 {%0,%1}, %2;" : "=f"(lo), "=f"(h) : "l"(v));
    return hi ? h : lo;
}

__device__ __forceinline__ float selu_f(float x) {
    const float s = 1.0507009873554805f;
    const float sa = 1.7580993408473766f;   // s * alpha
    return x > 0.f ? s * x : sa * (__expf(x) - 1.f);
}
// sigmoid(selu(x))
__device__ __forceinline__ float gate_f(float x) {
    float u = selu_f(x);
    return __fdividef(1.f, 1.f + __expf(-u));
}
__device__ __forceinline__ float tanh_f(float x) {
    return 1.f - 2.f * __fdividef(1.f, __expf(2.f * x) + 1.f);
}

// -------- init: zero h and c --------
__global__ void init_kernel() {
    int i = blockIdx.x * blockDim.x + threadIdx.x;
    if (i < BB * HID * HWSZ) {
        g_h[i] = 0.f;
        g_c[i] = 0.f;
    }
}

// -------- prep: fold BN into conv weights, permute pw weights --------
__global__ void prep_kernel(const float* __restrict__ dw_w,
                            const float* __restrict__ g1, const float* __restrict__ b1,
                            const float* __restrict__ m1, const float* __restrict__ v1,
                            const float* __restrict__ pw,
                            const float* __restrict__ g2, const float* __restrict__ b2,
                            const float* __restrict__ m2, const float* __restrict__ v2) {
    int tid = threadIdx.x;   // 256 threads
    if (tid < CC) {
        float s = g1[tid] * rsqrtf(v1[tid] + EPSBN);
        #pragma unroll
        for (int k = 0; k < 9; k++) g_dwf[tid * 9 + k] = dw_w[tid * 9 + k] * s;
        g_dwb[tid] = b1[tid] - m1[tid] * s;
    }
    {
        int oc = tid;                       // 0..255
        float s = g2[oc] * rsqrtf(v2[oc] + EPSBN);
        int gate = oc >> 6;
        int j = oc & 63;
        g_sp[j * 4 + gate] = b2[oc] - m2[oc] * s;
        for (int k = 0; k < 128; k++)
            g_wp[k * 256 + j * 4 + gate] = pw[oc * 128 + k] * s;
    }
}

// -------- depthwise 3x3 + BN1 + SELU  (z = concat(x_t, h)) --------
__global__ void dw_kernel(const float* __restrict__ x, int t) {
    int idx = blockIdx.x * blockDim.x + threadIdx.x;   // 1,048,576 threads, 4 px each
    int w4 = idx & 15;
    int y  = (idx >> 4) & 63;
    int c  = (idx >> 10) & 127;
    int b  = idx >> 17;
    int x0 = w4 << 2;

    const float* src = (c < CIN)
        ? x + ((size_t)(b * TT + t) * CIN + c) * HWSZ
        : g_h + ((size_t)b * HID + (c - CIN)) * HWSZ;

    float r0[6], r1[6], r2[6];
    int ybase = y * WW;
    bool yt = (y > 0), yb = (y < HH - 1);
    #pragma unroll
    for (int dx = 0; dx < 6; dx++) {
        int xx = x0 - 1 + dx;
        bool xv = (xx >= 0) && (xx < WW);
        r0[dx] = (yt && xv) ? __ldg(src + ybase - WW + xx) : 0.f;
        r1[dx] = xv ? __ldg(src + ybase + xx) : 0.f;
        r2[dx] = (yb && xv) ? __ldg(src + ybase + WW + xx) : 0.f;
    }

    float w[9];
    #pragma unroll
    for (int i = 0; i < 9; i++) w[i] = __ldg(g_dwf + c * 9 + i);
    float bias = __ldg(g_dwb + c);

    float4 o;
    float* op = &o.x;
    #pragma unroll
    for (int p = 0; p < 4; p++) {
        float acc = bias;
        acc += w[0] * r0[p] + w[1] * r0[p + 1] + w[2] * r0[p + 2];
        acc += w[3] * r1[p] + w[4] * r1[p + 1] + w[5] * r1[p + 2];
        acc += w[6] * r2[p] + w[7] * r2[p + 1] + w[8] * r2[p + 2];
        op[p] = selu_f(acc);
    }
    *(float4*)(g_dws + ((size_t)(b * CC + c)) * HWSZ + ybase + x0) = o;
}

// -------- pointwise GEMM (f32x2) + BN2 + SELU + sigmoid + LSTM cell --------
// Persistent: 128 CTAs x 256 threads, each CTA owns 2 of the 256 (b,tile) pairs.
// Weights staged once per CTA. Thread = (j-pair, pixel-group): owns 2 hidden
// channels x 4 gates x 16 pixels -> 64 FFMA2 per k for 6 LDS.128.
__global__ void __launch_bounds__(256, 1)
pw_kernel(float* __restrict__ out, int t) {
    extern __shared__ float sm[];
    float* Ws = sm;                // 32768 floats: [k][j][gate]
    float* Bs = sm + 32768;        // 16384 floats: [k][128 px]

    int tid = threadIdx.x;

    // stage weights once (128 KB)
    {
        const float4* wp4 = (const float4*)g_wp;
        float4* Ws4 = (float4*)Ws;
        #pragma unroll
        for (int i = 0; i < 32; i++) Ws4[tid + i * 256] = wp4[tid + i * 256];
    }

    int jp = tid >> 3;     // 0..31  -> j0 = 2*jp, j1 = 2*jp+1
    int g  = tid & 7;      // 0..7

    const float4* WsJ = (const float4*)Ws + 2 * jp;    // + k*64 (+0 / +1)
    const ulonglong2* Bu = (const ulonglong2*)Bs + g;  // + k*32 + i*8

    #pragma unroll 1
    for (int it = 0; it < 2; it++) {
        int tile = blockIdx.x * 2 + it;
        int b  = tile >> 5;
        int p0 = (tile & 31) << 7;

        // stage activation tile (64 KB)
        __syncthreads();   // previous tile's consumers done (and W staged on it=0)
        {
            const float* dwsb = g_dws + (size_t)b * CC * HWSZ + p0;
            float4* Bs4 = (float4*)Bs;
            #pragma unroll
            for (int i = 0; i < 16; i++) {
                int idx = tid + i * 256;          // 0..4095 float4s
                int k = idx >> 5, pp = idx & 31;
                Bs4[idx] = *(const float4*)(dwsb + (size_t)k * HWSZ + pp * 4);
            }
        }
        __syncthreads();

        ull acc[2][4][8];
        #pragma unroll
        for (int jj = 0; jj < 2; jj++)
            #pragma unroll
            for (int gt = 0; gt < 4; gt++)
                #pragma unroll
                for (int q = 0; q < 8; q++) acc[jj][gt][q] = 0ULL;

        #pragma unroll 2
        for (int k = 0; k < 128; k++) {
            float4 w0 = WsJ[k * 64];
            float4 w1 = WsJ[k * 64 + 1];
            ull wA[4], wB[4];
            wA[0] = pack2(w0.x, w0.x); wA[1] = pack2(w0.y, w0.y);
            wA[2] = pack2(w0.z, w0.z); wA[3] = pack2(w0.w, w0.w);
            wB[0] = pack2(w1.x, w1.x); wB[1] = pack2(w1.y, w1.y);
            wB[2] = pack2(w1.z, w1.z); wB[3] = pack2(w1.w, w1.w);
            #pragma unroll
            for (int i = 0; i < 4; i++) {
                ulonglong2 bv = Bu[k * 32 + i * 8];
                #pragma unroll
                for (int gt = 0; gt < 4; gt++) {
                    acc[0][gt][2 * i    ] = fma2(wA[gt], bv.x, acc[0][gt][2 * i    ]);
                    acc[0][gt][2 * i + 1] = fma2(wA[gt], bv.y, acc[0][gt][2 * i + 1]);
                    acc[1][gt][2 * i    ] = fma2(wB[gt], bv.x, acc[1][gt][2 * i    ]);
                    acc[1][gt][2 * i + 1] = fma2(wB[gt], bv.y, acc[1][gt][2 * i + 1]);
                }
            }
        }

        // epilogue: BN2 shift + selu + sigmoid -> gates; cell update; tanh; writes
        #pragma unroll
        for (int jj = 0; jj < 2; jj++) {
            int j = 2 * jp + jj;
            float4 sh = ((const float4*)g_sp)[j];
            size_t plane = ((size_t)b * HID + j) * HWSZ + p0;
            float* hb = g_h + plane;
            float* cb = g_c + plane;
            float* ob = out + ((size_t)(b * TT + t) * HID + j) * HWSZ + p0;

            #pragma unroll
            for (int i = 0; i < 4; i++) {
                int off = i * 32 + g * 4;
                float4 co = *(float4*)(cb + off);
                float4 cn, hn;
                const float* cop = &co.x;
                float* cnp = &cn.x;
                float* hnp = &hn.x;
                #pragma unroll
                for (int p = 0; p < 4; p++) {
                    int q = 2 * i + (p >> 1);
                    int hi = p & 1;
                    float zi = unpk(acc[jj][0][q], hi) + sh.x;
                    float zf = unpk(acc[jj][1][q], hi) + sh.y;
                    float zo = unpk(acc[jj][2][q], hi) + sh.z;
                    float zg = unpk(acc[jj][3][q], hi) + sh.w;
                    float gi = gate_f(zi);
                    float gf = gate_f(zf);
                    float go = gate_f(zo);
                    float gg = gate_f(zg);
                    float cv = gf * cop[p] + gi * gg;
                    cnp[p] = cv;
                    hnp[p] = go * tanh_f(cv);
                }
                *(float4*)(cb + off) = cn;
                *(float4*)(hb + off) = hn;
                *(float4*)(ob + off) = hn;
            }
        }
    }
}

// -------- launch --------
extern "C" void kernel_launch(void* const* d_in, const int* in_sizes, int n_in,
                              void* d_out, int out_size) {
    const float* x      = (const float*)d_in[0];
    const float* dw_w   = (const float*)d_in[1];
    const float* gamma1 = (const float*)d_in[2];
    const float* beta1  = (const float*)d_in[3];
    const float* mean1  = (const float*)d_in[4];
    const float* var1   = (const float*)d_in[5];
    const float* pw_w   = (const float*)d_in[6];
    const float* gamma2 = (const float*)d_in[7];
    const float* beta2  = (const float*)d_in[8];
    const float* mean2  = (const float*)d_in[9];
    const float* var2   = (const float*)d_in[10];
    float* out = (float*)d_out;

    cudaFuncSetAttribute(pw_kernel, cudaFuncAttributeMaxDynamicSharedMemorySize, 196608);

    init_kernel<<<(BB * HID * HWSZ + 511) / 512, 512>>>();
    prep_kernel<<<1, 256>>>(dw_w, gamma1, beta1, mean1, var1,
                            pw_w, gamma2, beta2, mean2, var2);

    for (int t = 0; t < TT; t++) {
        dw_kernel<<<4096, 256>>>(x, t);
        pw_kernel<<<128, 256, 196608>>>(out, t);
    }
}

// round 3
// speedup vs baseline: 1.0906x; 1.0906x over previous
#include <cuda_runtime.h>
#include <cuda_bf16.h>

// Problem constants
#define BB 8
#define TT 20
#define CIN 64
#define HID 64
#define HH 64
#define WW 64
#define HWSZ 4096          // 64*64
#define CC 128             // CIN + HID
#define C4 256             // 4*HID
#define EPSBN 1e-5f

typedef unsigned long long ull;

// -------- persistent device state (allocation-free scratch) --------
__device__ float g_h[BB * HID * HWSZ];        // hidden state   (8.4 MB)
__device__ float g_c[BB * HID * HWSZ];        // cell state     (8.4 MB)
__device__ float g_dws[BB * CC * HWSZ];       // selu(bn1(dwconv(z)))  (16.8 MB)
__device__ float g_wp[128 * 256];             // folded pw weights, layout [k][j][gate]
__device__ float g_sp[256];                   // folded bn2 shift, layout [j][gate]
__device__ float g_dwf[CC * 9];               // folded dw weights
__device__ float g_dwb[CC];                   // folded bn1 shift

// -------- helpers --------
__device__ __forceinline__ ull pack2(float a, float b) {
    ull r;
    asm("mov.b64 %0, {%1,%2};" : "=l"(r) : "f"(a), "f"(b));
    return r;
}
__device__ __forceinline__ ull fma2(ull a, ull b, ull c) {
    ull d;
    asm("fma.rn.f32x2 %0, %1, %2, %3;" : "=l"(d) : "l"(a), "l"(b), "l"(c));
    return d;
}
__device__ __forceinline__ float unpk(ull v, int hi) {
    float lo, h;
    asm("mov.b64 {%0,%1}, %2;" : "=f"(lo), "=f"(h) : "l"(v));
    return hi ? h : lo;
}

__device__ __forceinline__ float selu_f(float x) {
    const float s = 1.0507009873554805f;
    const float sa = 1.7580993408473766f;   // s * alpha
    return x > 0.f ? s * x : sa * (__expf(x) - 1.f);
}
// sigmoid(selu(x))
__device__ __forceinline__ float gate_f(float x) {
    float u = selu_f(x);
    return __fdividef(1.f, 1.f + __expf(-u));
}
__device__ __forceinline__ float tanh_f(float x) {
    return 1.f - 2.f * __fdividef(1.f, __expf(2.f * x) + 1.f);
}

// -------- init: zero h and c --------
__global__ void init_kernel() {
    int i = blockIdx.x * blockDim.x + threadIdx.x;
    if (i < BB * HID * HWSZ) {
        g_h[i] = 0.f;
        g_c[i] = 0.f;
    }
}

// -------- prep: fold BN into conv weights, permute pw weights --------
__global__ void prep_kernel(const float* __restrict__ dw_w,
                            const float* __restrict__ g1, const float* __restrict__ b1,
                            const float* __restrict__ m1, const float* __restrict__ v1,
                            const float* __restrict__ pw,
                            const float* __restrict__ g2, const float* __restrict__ b2,
                            const float* __restrict__ m2, const float* __restrict__ v2) {
    int tid = threadIdx.x;   // 256 threads
    if (tid < CC) {
        float s = g1[tid] * rsqrtf(v1[tid] + EPSBN);
        #pragma unroll
        for (int k = 0; k < 9; k++) g_dwf[tid * 9 + k] = dw_w[tid * 9 + k] * s;
        g_dwb[tid] = b1[tid] - m1[tid] * s;
    }
    {
        int oc = tid;                       // 0..255
        float s = g2[oc] * rsqrtf(v2[oc] + EPSBN);
        int gate = oc >> 6;
        int j = oc & 63;
        g_sp[j * 4 + gate] = b2[oc] - m2[oc] * s;
        for (int k = 0; k < 128; k++)
            g_wp[k * 256 + j * 4 + gate] = pw[oc * 128 + k] * s;
    }
}

// -------- depthwise 3x3 + BN1 + SELU  (z = concat(x_t, h)) --------
__global__ void dw_kernel(const float* __restrict__ x, int t) {
    int idx = blockIdx.x * blockDim.x + threadIdx.x;   // 1,048,576 threads, 4 px each
    int w4 = idx & 15;
    int y  = (idx >> 4) & 63;
    int c  = (idx >> 10) & 127;
    int b  = idx >> 17;
    int x0 = w4 << 2;

    const float* src = (c < CIN)
        ? x + ((size_t)(b * TT + t) * CIN + c) * HWSZ
        : g_h + ((size_t)b * HID + (c - CIN)) * HWSZ;

    float r0[6], r1[6], r2[6];
    int ybase = y * WW;
    bool yt = (y > 0), yb = (y < HH - 1);
    #pragma unroll
    for (int dx = 0; dx < 6; dx++) {
        int xx = x0 - 1 + dx;
        bool xv = (xx >= 0) && (xx < WW);
        r0[dx] = (yt && xv) ? __ldg(src + ybase - WW + xx) : 0.f;
        r1[dx] = xv ? __ldg(src + ybase + xx) : 0.f;
        r2[dx] = (yb && xv) ? __ldg(src + ybase + WW + xx) : 0.f;
    }

    float w[9];
    #pragma unroll
    for (int i = 0; i < 9; i++) w[i] = __ldg(g_dwf + c * 9 + i);
    float bias = __ldg(g_dwb + c);

    float4 o;
    float* op = &o.x;
    #pragma unroll
    for (int p = 0; p < 4; p++) {
        float acc = bias;
        acc += w[0] * r0[p] + w[1] * r0[p + 1] + w[2] * r0[p + 2];
        acc += w[3] * r1[p] + w[4] * r1[p + 1] + w[5] * r1[p + 2];
        acc += w[6] * r2[p] + w[7] * r2[p + 1] + w[8] * r2[p + 2];
        op[p] = selu_f(acc);
    }
    *(float4*)(g_dws + ((size_t)(b * CC + c)) * HWSZ + ybase + x0) = o;
}

// -------- pointwise GEMM (f32x2) + BN2 + SELU + sigmoid + LSTM cell --------
// Persistent: 148 CTAs x 512 threads; 256 (b,tile) pairs, CTA i does tiles
// i, i+148. Weights (128KB) staged once per CTA. Thread = (jp, g):
// 2 hidden channels x 4 gates x 8 pixels. Lanes 0-15 / 16-31 of a warp share
// g -> B reads broadcast-dedup; weight reads 16-way broadcast.
__global__ void __launch_bounds__(512, 1)
pw_kernel(float* __restrict__ out, int t) {
    extern __shared__ float sm[];
    float* Ws = sm;                // 32768 floats: [k][j][gate]
    float* Bs = sm + 32768;        // 16384 floats: [k][128 px]

    int tid = threadIdx.x;

    // stage weights once (128 KB)
    {
        const float4* wp4 = (const float4*)g_wp;
        float4* Ws4 = (float4*)Ws;
        #pragma unroll
        for (int i = 0; i < 16; i++) Ws4[tid + i * 512] = wp4[tid + i * 512];
    }

    int jp = tid >> 4;     // 0..31  -> channels 2jp, 2jp+1
    int g  = tid & 15;     // 0..15  -> pixels g*8 .. g*8+7

    const float4* WsJ = (const float4*)Ws + 2 * jp;      // + k*64 (+0/+1)
    const ulonglong2* Bu = (const ulonglong2*)Bs + 2 * g; // + k*32 (+0/+1)

    for (int tile = blockIdx.x; tile < 256; tile += 148) {
        int b  = tile >> 5;
        int p0 = (tile & 31) << 7;

        __syncthreads();   // weights staged / previous tile consumers done
        // stage activation tile (64 KB)
        {
            const float* dwsb = g_dws + (size_t)b * CC * HWSZ + p0;
            float4* Bs4 = (float4*)Bs;
            #pragma unroll
            for (int i = 0; i < 8; i++) {
                int idx = tid + i * 512;          // 0..4095 float4s
                int k = idx >> 5, pp = idx & 31;
                Bs4[idx] = *(const float4*)(dwsb + (size_t)k * HWSZ + pp * 4);
            }
        }
        __syncthreads();

        ull acc[2][4][4];   // [ch][gate][px-pair]
        #pragma unroll
        for (int jj = 0; jj < 2; jj++)
            #pragma unroll
            for (int gt = 0; gt < 4; gt++)
                #pragma unroll
                for (int q = 0; q < 4; q++) acc[jj][gt][q] = 0ULL;

        #pragma unroll 1
        for (int k = 0; k < 128; k++) {
            float4 w0 = WsJ[k * 64];
            float4 w1 = WsJ[k * 64 + 1];
            ulonglong2 b0 = Bu[k * 32];
            ulonglong2 b1 = Bu[k * 32 + 1];
            ull wA[4], wB[4];
            wA[0] = pack2(w0.x, w0.x); wA[1] = pack2(w0.y, w0.y);
            wA[2] = pack2(w0.z, w0.z); wA[3] = pack2(w0.w, w0.w);
            wB[0] = pack2(w1.x, w1.x); wB[1] = pack2(w1.y, w1.y);
            wB[2] = pack2(w1.z, w1.z); wB[3] = pack2(w1.w, w1.w);
            #pragma unroll
            for (int gt = 0; gt < 4; gt++) {
                acc[0][gt][0] = fma2(wA[gt], b0.x, acc[0][gt][0]);
                acc[0][gt][1] = fma2(wA[gt], b0.y, acc[0][gt][1]);
                acc[0][gt][2] = fma2(wA[gt], b1.x, acc[0][gt][2]);
                acc[0][gt][3] = fma2(wA[gt], b1.y, acc[0][gt][3]);
                acc[1][gt][0] = fma2(wB[gt], b0.x, acc[1][gt][0]);
                acc[1][gt][1] = fma2(wB[gt], b0.y, acc[1][gt][1]);
                acc[1][gt][2] = fma2(wB[gt], b1.x, acc[1][gt][2]);
                acc[1][gt][3] = fma2(wB[gt], b1.y, acc[1][gt][3]);
            }
        }

        // epilogue: BN2 shift + selu + sigmoid -> gates; cell update; tanh
        #pragma unroll
        for (int jj = 0; jj < 2; jj++) {
            int j = 2 * jp + jj;
            float4 sh = ((const float4*)g_sp)[j];
            size_t plane = ((size_t)b * HID + j) * HWSZ + p0;
            float* hb = g_h + plane;
            float* cb = g_c + plane;
            float* ob = out + ((size_t)(b * TT + t) * HID + j) * HWSZ + p0;

            #pragma unroll
            for (int i = 0; i < 2; i++) {
                int off = g * 8 + i * 4;
                float4 co = *(float4*)(cb + off);
                float4 cn, hn;
                const float* cop = &co.x;
                float* cnp = &cn.x;
                float* hnp = &hn.x;
                #pragma unroll
                for (int l = 0; l < 4; l++) {
                    int q = i * 2 + (l >> 1);
                    int hi = l & 1;
                    float zi = unpk(acc[jj][0][q], hi) + sh.x;
                    float zf = unpk(acc[jj][1][q], hi) + sh.y;
                    float zo = unpk(acc[jj][2][q], hi) + sh.z;
                    float zg = unpk(acc[jj][3][q], hi) + sh.w;
                    float gi = gate_f(zi);
                    float gf = gate_f(zf);
                    float go = gate_f(zo);
                    float gg = gate_f(zg);
                    float cv = gf * cop[l] + gi * gg;
                    cnp[l] = cv;
                    hnp[l] = go * tanh_f(cv);
                }
                *(float4*)(cb + off) = cn;
                *(float4*)(hb + off) = hn;
                *(float4*)(ob + off) = hn;
            }
        }
    }
}

// -------- launch --------
extern "C" void kernel_launch(void* const* d_in, const int* in_sizes, int n_in,
                              void* d_out, int out_size) {
    const float* x      = (const float*)d_in[0];
    const float* dw_w   = (const float*)d_in[1];
    const float* gamma1 = (const float*)d_in[2];
    const float* beta1  = (const float*)d_in[3];
    const float* mean1  = (const float*)d_in[4];
    const float* var1   = (const float*)d_in[5];
    const float* pw_w   = (const float*)d_in[6];
    const float* gamma2 = (const float*)d_in[7];
    const float* beta2  = (const float*)d_in[8];
    const float* mean2  = (const float*)d_in[9];
    const float* var2   = (const float*)d_in[10];
    float* out = (float*)d_out;

    cudaFuncSetAttribute(pw_kernel, cudaFuncAttributeMaxDynamicSharedMemorySize, 196608);

    init_kernel<<<(BB * HID * HWSZ + 511) / 512, 512>>>();
    prep_kernel<<<1, 256>>>(dw_w, gamma1, beta1, mean1, var1,
                            pw_w, gamma2, beta2, mean2, var2);

    for (int t = 0; t < TT; t++) {
        dw_kernel<<<4096, 256>>>(x, t);
        pw_kernel<<<148, 512, 196608>>>(out, t);
    }
}

// round 5
// speedup vs baseline: 1.6087x; 1.4751x over previous
#include <cuda_runtime.h>
#include <cuda_bf16.h>
#include <cstdint>

// Problem constants
#define BB 8
#define TT 20
#define CIN 64
#define HID 64
#define HH 64
#define WW 64
#define HWSZ 4096          // 64*64
#define CC 128             // CIN + HID
#define C4 256             // 4*HID
#define EPSBN 1e-5f

typedef unsigned long long ull;

// -------- persistent device state --------
__device__ float g_h[BB * HID * HWSZ];
__device__ float g_c[BB * HID * HWSZ];
__device__ float g_dws[BB * CC * HWSZ];         // selu(bn1(dw(z))), layout [b][k][px]
__device__ unsigned short g_wb[65536];          // bf16 W: [0,32768) hi, [32768,65536) lo (shorts), swizzled
__device__ float g_sp[256];                     // bn2 shift, [j*4+gate]
__device__ float g_dwf[CC * 9];
__device__ float g_dwb[CC];

// -------- helpers --------
__device__ __forceinline__ uint32_t smem_u32(const void* p) {
    uint32_t a;
    asm("{ .reg .u64 t; cvta.to.shared.u64 t, %1; cvt.u32.u64 %0, t; }" : "=r"(a) : "l"(p));
    return a;
}
__device__ __forceinline__ void ldm4(uint32_t* r, uint32_t a) {
    asm volatile("ldmatrix.sync.aligned.m8n8.x4.shared.b16 {%0,%1,%2,%3}, [%4];"
        : "=r"(r[0]), "=r"(r[1]), "=r"(r[2]), "=r"(r[3]) : "r"(a));
}
__device__ __forceinline__ void mma_bf16(float* d, const uint32_t* a, uint32_t b0, uint32_t b1) {
    asm volatile("mma.sync.aligned.m16n8k16.row.col.f32.bf16.bf16.f32 "
        "{%0,%1,%2,%3}, {%4,%5,%6,%7}, {%8,%9}, {%0,%1,%2,%3};"
        : "+f"(d[0]), "+f"(d[1]), "+f"(d[2]), "+f"(d[3])
        : "r"(a[0]), "r"(a[1]), "r"(a[2]), "r"(a[3]), "r"(b0), "r"(b1));
}

__device__ __forceinline__ float selu_f(float x) {
    const float s = 1.0507009873554805f;
    const float sa = 1.7580993408473766f;
    return x > 0.f ? s * x : sa * (__expf(x) - 1.f);
}
__device__ __forceinline__ float gate_f(float x) {
    float u = selu_f(x);
    return __fdividef(1.f, 1.f + __expf(-u));
}
__device__ __forceinline__ float tanh_f(float x) {
    return 1.f - 2.f * __fdividef(1.f, __expf(2.f * x) + 1.f);
}

// -------- init --------
__global__ void init_kernel() {
    int i = blockIdx.x * blockDim.x + threadIdx.x;
    if (i < BB * HID * HWSZ) { g_h[i] = 0.f; g_c[i] = 0.f; }
}

// -------- prep: fold BN; build swizzled bf16 hi/lo W; dw folds --------
__global__ void prep_kernel(const float* __restrict__ dw_w,
                            const float* __restrict__ g1, const float* __restrict__ b1,
                            const float* __restrict__ m1, const float* __restrict__ v1,
                            const float* __restrict__ pw,
                            const float* __restrict__ g2, const float* __restrict__ b2,
                            const float* __restrict__ m2, const float* __restrict__ v2) {
    int tid = threadIdx.x;   // 256
    if (tid < CC) {
        float s = g1[tid] * rsqrtf(v1[tid] + EPSBN);
        #pragma unroll
        for (int k = 0; k < 9; k++) g_dwf[tid * 9 + k] = dw_w[tid * 9 + k] * s;
        g_dwb[tid] = b1[tid] - m1[tid] * s;
    }
    {
        int oc = tid;                       // original oc = gate*64 + j
        float s = g2[oc] * rsqrtf(v2[oc] + EPSBN);
        int gate = oc >> 6;
        int j = oc & 63;
        int r = j * 4 + gate;               // W smem row / D column index
        g_sp[r] = b2[oc] - m2[oc] * s;
        for (int k = 0; k < 128; k++) {
            float wv = pw[oc * 128 + k] * s;
            __nv_bfloat16 hi = __float2bfloat16(wv);
            __nv_bfloat16 lo = __float2bfloat16(wv - __bfloat162float(hi));
            // row-major [r][k] bf16, 256B/row, 16B-chunk XOR swizzle
            uint32_t off = (uint32_t)r * 256 + (uint32_t)(((k >> 3) ^ (r & 7)) * 16) + (k & 7) * 2;
            g_wb[off >> 1] = *(unsigned short*)&hi;
            g_wb[32768 + (off >> 1)] = *(unsigned short*)&lo;
        }
    }
}

// -------- depthwise 3x3 + BN1 + SELU --------
__global__ void dw_kernel(const float* __restrict__ x, int t) {
    int idx = blockIdx.x * blockDim.x + threadIdx.x;
    int w4 = idx & 15;
    int y  = (idx >> 4) & 63;
    int c  = (idx >> 10) & 127;
    int b  = idx >> 17;
    int x0 = w4 << 2;

    const float* src = (c < CIN)
        ? x + ((size_t)(b * TT + t) * CIN + c) * HWSZ
        : g_h + ((size_t)b * HID + (c - CIN)) * HWSZ;

    float r0[6], r1[6], r2[6];
    int ybase = y * WW;
    bool yt = (y > 0), yb = (y < HH - 1);
    #pragma unroll
    for (int dx = 0; dx < 6; dx++) {
        int xx = x0 - 1 + dx;
        bool xv = (xx >= 0) && (xx < WW);
        r0[dx] = (yt && xv) ? __ldg(src + ybase - WW + xx) : 0.f;
        r1[dx] = xv ? __ldg(src + ybase + xx) : 0.f;
        r2[dx] = (yb && xv) ? __ldg(src + ybase + WW + xx) : 0.f;
    }
    float w[9];
    #pragma unroll
    for (int i = 0; i < 9; i++) w[i] = __ldg(g_dwf + c * 9 + i);
    float bias = __ldg(g_dwb + c);

    float4 o; float* op = &o.x;
    #pragma unroll
    for (int p = 0; p < 4; p++) {
        float acc = bias;
        acc += w[0]*r0[p] + w[1]*r0[p+1] + w[2]*r0[p+2];
        acc += w[3]*r1[p] + w[4]*r1[p+1] + w[5]*r1[p+2];
        acc += w[6]*r2[p] + w[7]*r2[p+1] + w[8]*r2[p+2];
        op[p] = selu_f(acc);
    }
    *(float4*)(g_dws + ((size_t)(b * CC + c)) * HWSZ + ybase + x0) = o;
}

// -------- HMMA pointwise GEMM + LSTM epilogue --------
// Persistent 148 CTAs x 512 threads. Tile = (batch b, 128 px) x 256 oc x 128 k.
// smem: W hi [0,64K), W lo [64K,128K), A hi [128K,160K), A lo [160K,192K).
// bf16 two-fold split: D = Ah*Wh + Ah*Wl + Al*Wh  (fp32 accumulate).
// Warp (pb = w&3, ob = w>>2): 32px x 64oc block; mma.m16n8k16 fragments.
__global__ void __launch_bounds__(512, 1)
pw_kernel(float* __restrict__ out, int t) {
    extern __shared__ char smem[];
    uint32_t sb = smem_u32(smem);
    int tid = threadIdx.x;
    int w = tid >> 5, lane = tid & 31;
    int pb = w & 3, ob = w >> 2;

    // stage weights once (128 KB, pre-swizzled -> linear copy)
    {
        const float4* src = (const float4*)g_wb;
        float4* dst = (float4*)smem;
        #pragma unroll
        for (int i = 0; i < 16; i++) dst[tid + i * 512] = src[tid + i * 512];
    }

    // ldmatrix per-lane address components
    const uint32_t AHI = sb + 131072;
    int arow = pb * 32 + (lane & 15);
    int apar = (lane >> 4) & 1;
    int asw  = arow & 7;
    int wrow = ob * 64 + (lane & 7) + (((lane >> 4) & 1) << 3);
    int wpar = (lane >> 3) & 1;
    int wsw  = wrow & 7;

    for (int tile = blockIdx.x; tile < 256; tile += 148) {
        int b  = tile >> 5;
        int p0 = (tile & 31) << 7;

        __syncthreads();   // previous tile's A readers done (no-op on first)

        // ---- build A: thread = (px = pb*32+lane, kg = ob); 32 k values ----
        {
            int px = pb * 32 + lane;
            const float* src = g_dws + ((size_t)b * CC + ob * 32) * HWSZ + p0 + px;
            float a[32];
            #pragma unroll
            for (int i = 0; i < 32; i++) a[i] = __ldg(src + (size_t)i * HWSZ);
            uint32_t rowb = px * 256;
            int pxsw = px & 7;
            #pragma unroll
            for (int p = 0; p < 16; p++) {
                float a0 = a[2*p], a1 = a[2*p+1];
                uint32_t h2;
                asm("cvt.rn.bf16x2.f32 %0, %1, %2;" : "=r"(h2) : "f"(a1), "f"(a0));
                float h0 = __uint_as_float(h2 << 16);
                float h1 = __uint_as_float(h2 & 0xFFFF0000u);
                float l0 = a0 - h0, l1 = a1 - h1;
                uint32_t l2;
                asm("cvt.rn.bf16x2.f32 %0, %1, %2;" : "=r"(l2) : "f"(l1), "f"(l0));
                uint32_t chunk = (uint32_t)((ob * 4 + (p >> 2)) ^ pxsw);
                uint32_t off = rowb + chunk * 16 + (p & 3) * 4;
                *(uint32_t*)(smem + 131072 + off) = h2;
                *(uint32_t*)(smem + 163840 + off) = l2;
            }
        }
        __syncthreads();

        // ---- MMA mainloop ----
        float acc[2][8][4];
        #pragma unroll
        for (int mt = 0; mt < 2; mt++)
            #pragma unroll
            for (int nt = 0; nt < 8; nt++)
                #pragma unroll
                for (int q = 0; q < 4; q++) acc[mt][nt][q] = 0.f;

        #pragma unroll
        for (int kc = 0; kc < 8; kc++) {
            uint32_t ah[2][4], al[2][4];
            #pragma unroll
            for (int mt = 0; mt < 2; mt++) {
                uint32_t chunk = (uint32_t)((2 * kc + apar) ^ asw);
                uint32_t addr = AHI + (uint32_t)(arow + mt * 16) * 256 + chunk * 16;
                ldm4(ah[mt], addr);
                ldm4(al[mt], addr + 32768);
            }
            #pragma unroll
            for (int np = 0; np < 4; np++) {
                uint32_t chunk = (uint32_t)((2 * kc + wpar) ^ wsw);
                uint32_t addr = sb + (uint32_t)(wrow + np * 16) * 256 + chunk * 16;
                uint32_t wf[4];
                ldm4(wf, addr);                       // W hi
                #pragma unroll
                for (int mt = 0; mt < 2; mt++) {
                    mma_bf16(acc[mt][np*2],   ah[mt], wf[0], wf[1]);
                    mma_bf16(acc[mt][np*2+1], ah[mt], wf[2], wf[3]);
                    mma_bf16(acc[mt][np*2],   al[mt], wf[0], wf[1]);
                    mma_bf16(acc[mt][np*2+1], al[mt], wf[2], wf[3]);
                }
                ldm4(wf, addr + 65536);               // W lo
                #pragma unroll
                for (int mt = 0; mt < 2; mt++) {
                    mma_bf16(acc[mt][np*2],   ah[mt], wf[0], wf[1]);
                    mma_bf16(acc[mt][np*2+1], ah[mt], wf[2], wf[3]);
                }
            }
        }

        // ---- epilogue: fragment -> gates via shfl.xor(1), LSTM, stores ----
        #pragma unroll
        for (int mt = 0; mt < 2; mt++) {
            #pragma unroll
            for (int nt = 0; nt < 8; nt++) {
                float* a = acc[mt][nt];
                int ocb = ob * 64 + nt * 8 + 2 * (lane & 3);
                float sp0 = __ldg(g_sp + ocb);
                float sp1 = __ldg(g_sp + ocb + 1);
                float v0 = a[0] + sp0, v1 = a[1] + sp1;
                float v2 = a[2] + sp0, v3 = a[3] + sp1;
                float e0 = __shfl_xor_sync(0xFFFFFFFFu, v0, 1);
                float e1 = __shfl_xor_sync(0xFFFFFFFFu, v1, 1);
                float e2 = __shfl_xor_sync(0xFFFFFFFFu, v2, 1);
                float e3 = __shfl_xor_sync(0xFFFFFFFFu, v3, 1);
                float zi, zf, zo, zg; int rr;
                if ((lane & 1) == 0) { zi = v0; zf = v1; zo = e0; zg = e1; rr = lane >> 2; }
                else                 { zi = e2; zf = e3; zo = v2; zg = v3; rr = (lane >> 2) + 8; }
                int j  = ob * 16 + nt * 2 + ((lane >> 1) & 1);
                int px = pb * 32 + mt * 16 + rr;
                size_t plane = ((size_t)b * HID + j) * HWSZ + p0 + px;
                float co = __ldg(g_c + plane);
                float gi = gate_f(zi);
                float gf = gate_f(zf);
                float go = gate_f(zo);
                float gg = gate_f(zg);
                float cv = gf * co + gi * gg;
                float hv = go * tanh_f(cv);
                g_c[plane] = cv;
                g_h[plane] = hv;
                out[((size_t)(b * TT + t) * HID + j) * HWSZ + p0 + px] = hv;
            }
        }
    }
}

// -------- launch --------
extern "C" void kernel_launch(void* const* d_in, const int* in_sizes, int n_in,
                              void* d_out, int out_size) {
    const float* x      = (const float*)d_in[0];
    const float* dw_w   = (const float*)d_in[1];
    const float* gamma1 = (const float*)d_in[2];
    const float* beta1  = (const float*)d_in[3];
    const float* mean1  = (const float*)d_in[4];
    const float* var1   = (const float*)d_in[5];
    const float* pw_w   = (const float*)d_in[6];
    const float* gamma2 = (const float*)d_in[7];
    const float* beta2  = (const float*)d_in[8];
    const float* mean2  = (const float*)d_in[9];
    const float* var2   = (const float*)d_in[10];
    float* out = (float*)d_out;

    cudaFuncSetAttribute(pw_kernel, cudaFuncAttributeMaxDynamicSharedMemorySize, 196608);

    init_kernel<<<(BB * HID * HWSZ + 511) / 512, 512>>>();
    prep_kernel<<<1, 256>>>(dw_w, gamma1, beta1, mean1, var1,
                            pw_w, gamma2, beta2, mean2, var2);

    for (int t = 0; t < TT; t++) {
        dw_kernel<<<4096, 256>>>(x, t);
        pw_kernel<<<148, 512, 196608>>>(out, t);
    }
}

// round 6
// speedup vs baseline: 1.6100x; 1.0008x over previous
#include <cuda_runtime.h>
#include <cuda_bf16.h>
#include <cstdint>

// Problem constants
#define BB 8
#define TT 20
#define CIN 64
#define HID 64
#define HH 64
#define WW 64
#define HWSZ 4096          // 64*64
#define CC 128             // CIN + HID
#define C4 256             // 4*HID
#define EPSBN 1e-5f

typedef unsigned long long ull;

// -------- persistent device state --------
__device__ float g_h[BB * HID * HWSZ];
__device__ float g_c[BB * HID * HWSZ];
__device__ float g_dws[BB * CC * HWSZ];         // selu(bn1(dw(z))), layout [b][k][px]
__device__ unsigned short g_wb[65536];          // bf16 W: [0,32768) hi, [32768,65536) lo (shorts), swizzled
__device__ float g_sp[256];                     // bn2 shift, [j*4+gate]
__device__ float g_dwf[CC * 9];
__device__ float g_dwb[CC];

// -------- helpers --------
__device__ __forceinline__ uint32_t smem_u32(const void* p) {
    uint32_t a;
    asm("{ .reg .u64 t; cvta.to.shared.u64 t, %1; cvt.u32.u64 %0, t; }" : "=r"(a) : "l"(p));
    return a;
}
__device__ __forceinline__ void ldm4(uint32_t* r, uint32_t a) {
    asm volatile("ldmatrix.sync.aligned.m8n8.x4.shared.b16 {%0,%1,%2,%3}, [%4];"
        : "=r"(r[0]), "=r"(r[1]), "=r"(r[2]), "=r"(r[3]) : "r"(a));
}
__device__ __forceinline__ void mma_bf16(float* d, const uint32_t* a, uint32_t b0, uint32_t b1) {
    asm volatile("mma.sync.aligned.m16n8k16.row.col.f32.bf16.bf16.f32 "
        "{%0,%1,%2,%3}, {%4,%5,%6,%7}, {%8,%9}, {%0,%1,%2,%3};"
        : "+f"(d[0]), "+f"(d[1]), "+f"(d[2]), "+f"(d[3])
        : "r"(a[0]), "r"(a[1]), "r"(a[2]), "r"(a[3]), "r"(b0), "r"(b1));
}
__device__ __forceinline__ float tanha(float x) {
    float r;
    asm("tanh.approx.f32 %0, %1;" : "=f"(r) : "f"(x));
    return r;
}

__device__ __forceinline__ float selu_f(float x) {
    const float s = 1.0507009873554805f;
    const float sa = 1.7580993408473766f;
    return x > 0.f ? s * x : sa * (__expf(x) - 1.f);
}
// exact sigmoid(selu(x))  (used for i, f, g gates feeding the recurrence)
__device__ __forceinline__ float gate_f(float x) {
    float u = selu_f(x);
    return __fdividef(1.f, 1.f + __expf(-u));
}
// fast sigmoid(selu(x)) via tanh.approx (o gate only; no recurrence accumulation)
__device__ __forceinline__ float gate_fast(float x) {
    float u = selu_f(x);
    return 0.5f + 0.5f * tanha(0.5f * u);
}

// -------- init --------
__global__ void init_kernel() {
    int i = blockIdx.x * blockDim.x + threadIdx.x;
    if (i < BB * HID * HWSZ) { g_h[i] = 0.f; g_c[i] = 0.f; }
}

// -------- prep: fold BN; build swizzled bf16 hi/lo W; dw folds --------
__global__ void prep_kernel(const float* __restrict__ dw_w,
                            const float* __restrict__ g1, const float* __restrict__ b1,
                            const float* __restrict__ m1, const float* __restrict__ v1,
                            const float* __restrict__ pw,
                            const float* __restrict__ g2, const float* __restrict__ b2,
                            const float* __restrict__ m2, const float* __restrict__ v2) {
    int tid = threadIdx.x;   // 256
    if (tid < CC) {
        float s = g1[tid] * rsqrtf(v1[tid] + EPSBN);
        #pragma unroll
        for (int k = 0; k < 9; k++) g_dwf[tid * 9 + k] = dw_w[tid * 9 + k] * s;
        g_dwb[tid] = b1[tid] - m1[tid] * s;
    }
    {
        int oc = tid;                       // original oc = gate*64 + j
        float s = g2[oc] * rsqrtf(v2[oc] + EPSBN);
        int gate = oc >> 6;
        int j = oc & 63;
        int r = j * 4 + gate;               // W smem row / D column index
        g_sp[r] = b2[oc] - m2[oc] * s;
        for (int k = 0; k < 128; k++) {
            float wv = pw[oc * 128 + k] * s;
            __nv_bfloat16 hi = __float2bfloat16(wv);
            __nv_bfloat16 lo = __float2bfloat16(wv - __bfloat162float(hi));
            // row-major [r][k] bf16, 256B/row, 16B-chunk XOR swizzle
            uint32_t off = (uint32_t)r * 256 + (uint32_t)(((k >> 3) ^ (r & 7)) * 16) + (k & 7) * 2;
            g_wb[off >> 1] = *(unsigned short*)&hi;
            g_wb[32768 + (off >> 1)] = *(unsigned short*)&lo;
        }
    }
}

// -------- depthwise 3x3 + BN1 + SELU --------
__global__ void dw_kernel(const float* __restrict__ x, int t) {
    int idx = blockIdx.x * blockDim.x + threadIdx.x;
    int w4 = idx & 15;
    int y  = (idx >> 4) & 63;
    int c  = (idx >> 10) & 127;
    int b  = idx >> 17;
    int x0 = w4 << 2;

    const float* src = (c < CIN)
        ? x + ((size_t)(b * TT + t) * CIN + c) * HWSZ
        : g_h + ((size_t)b * HID + (c - CIN)) * HWSZ;

    float r0[6], r1[6], r2[6];
    int ybase = y * WW;
    bool yt = (y > 0), yb = (y < HH - 1);
    #pragma unroll
    for (int dx = 0; dx < 6; dx++) {
        int xx = x0 - 1 + dx;
        bool xv = (xx >= 0) && (xx < WW);
        r0[dx] = (yt && xv) ? __ldg(src + ybase - WW + xx) : 0.f;
        r1[dx] = xv ? __ldg(src + ybase + xx) : 0.f;
        r2[dx] = (yb && xv) ? __ldg(src + ybase + WW + xx) : 0.f;
    }
    float w[9];
    #pragma unroll
    for (int i = 0; i < 9; i++) w[i] = __ldg(g_dwf + c * 9 + i);
    float bias = __ldg(g_dwb + c);

    float4 o; float* op = &o.x;
    #pragma unroll
    for (int p = 0; p < 4; p++) {
        float acc = bias;
        acc += w[0]*r0[p] + w[1]*r0[p+1] + w[2]*r0[p+2];
        acc += w[3]*r1[p] + w[4]*r1[p+1] + w[5]*r1[p+2];
        acc += w[6]*r2[p] + w[7]*r2[p+1] + w[8]*r2[p+2];
        op[p] = selu_f(acc);
    }
    *(float4*)(g_dws + ((size_t)(b * CC + c)) * HWSZ + ybase + x0) = o;
}

// -------- HMMA pointwise GEMM + LSTM epilogue, cross-tile pipelined --------
// Persistent 148 CTAs x 512 threads. Tile = (batch b, 128 px) x 256 oc x 128 k.
// smem: W hi [0,64K), W lo [64K,128K), A hi [128K,160K), A lo [160K,192K).
// bf16 two-fold split: D = Ah*Wh + Ah*Wl + Al*Wh  (fp32 accumulate).
// A(tile i+1) is built inside the epilogue of tile i (LDG ring hidden under MUFU).
__global__ void __launch_bounds__(512, 1)
pw_kernel(float* __restrict__ out, int t) {
    extern __shared__ char smem[];
    uint32_t sb = smem_u32(smem);
    int tid = threadIdx.x;
    int w = tid >> 5, lane = tid & 31;
    int pb = w & 3, ob = w >> 2;

    // stage weights once (128 KB, pre-swizzled -> linear copy)
    {
        const float4* src = (const float4*)g_wb;
        float4* dst = (float4*)smem;
        #pragma unroll
        for (int i = 0; i < 16; i++) dst[tid + i * 512] = src[tid + i * 512];
    }

    // ldmatrix per-lane address components
    const uint32_t AHI = sb + 131072;
    int arow = pb * 32 + (lane & 15);
    int apar = (lane >> 4) & 1;
    int asw  = arow & 7;
    int wrow = ob * 64 + (lane & 7) + (((lane >> 4) & 1) << 3);
    int wpar = (lane >> 3) & 1;
    int wsw  = wrow & 7;

    // A-build lane constants: this thread owns px, k = ob*32 .. ob*32+31
    int px = pb * 32 + lane;
    uint32_t rowb = (uint32_t)px * 256;
    int pxsw = px & 7;

    // ---- prologue: build A for first tile ----
    {
        int tile = blockIdx.x;              // < 256 always
        int b  = tile >> 5;
        int p0 = (tile & 31) << 7;
        const float* src = g_dws + ((size_t)b * CC + ob * 32) * HWSZ + p0 + px;
        float a[32];
        #pragma unroll
        for (int i = 0; i < 32; i++) a[i] = __ldg(src + (size_t)i * HWSZ);
        #pragma unroll
        for (int p = 0; p < 16; p++) {
            float a0 = a[2*p], a1 = a[2*p+1];
            uint32_t h2;
            asm("cvt.rn.bf16x2.f32 %0, %1, %2;" : "=r"(h2) : "f"(a1), "f"(a0));
            float l0 = a0 - __uint_as_float(h2 << 16);
            float l1 = a1 - __uint_as_float(h2 & 0xFFFF0000u);
            uint32_t l2;
            asm("cvt.rn.bf16x2.f32 %0, %1, %2;" : "=r"(l2) : "f"(l1), "f"(l0));
            uint32_t chunk = (uint32_t)((ob * 4 + (p >> 2)) ^ pxsw);
            uint32_t off = rowb + chunk * 16 + (p & 3) * 4;
            *(uint32_t*)(smem + 131072 + off) = h2;
            *(uint32_t*)(smem + 163840 + off) = l2;
        }
    }
    __syncthreads();

    for (int tile = blockIdx.x; tile < 256; tile += 148) {
        int b  = tile >> 5;
        int p0 = (tile & 31) << 7;
        int ntile = tile + 148;
        bool hasNext = ntile < 256;
        int nb  = ntile >> 5;
        int np0 = (ntile & 31) << 7;

        // ---- MMA mainloop (A of this tile already in smem) ----
        float acc[2][8][4];
        #pragma unroll
        for (int mt = 0; mt < 2; mt++)
            #pragma unroll
            for (int nt = 0; nt < 8; nt++)
                #pragma unroll
                for (int q = 0; q < 4; q++) acc[mt][nt][q] = 0.f;

        #pragma unroll
        for (int kc = 0; kc < 8; kc++) {
            uint32_t ah[2][4], al[2][4];
            #pragma unroll
            for (int mt = 0; mt < 2; mt++) {
                uint32_t chunk = (uint32_t)((2 * kc + apar) ^ asw);
                uint32_t addr = AHI + (uint32_t)(arow + mt * 16) * 256 + chunk * 16;
                ldm4(ah[mt], addr);
                ldm4(al[mt], addr + 32768);
            }
            #pragma unroll
            for (int np = 0; np < 4; np++) {
                uint32_t chunk = (uint32_t)((2 * kc + wpar) ^ wsw);
                uint32_t addr = sb + (uint32_t)(wrow + np * 16) * 256 + chunk * 16;
                uint32_t wf[4];
                ldm4(wf, addr);                       // W hi
                #pragma unroll
                for (int mt = 0; mt < 2; mt++) {
                    mma_bf16(acc[mt][np*2],   ah[mt], wf[0], wf[1]);
                    mma_bf16(acc[mt][np*2+1], ah[mt], wf[2], wf[3]);
                    mma_bf16(acc[mt][np*2],   al[mt], wf[0], wf[1]);
                    mma_bf16(acc[mt][np*2+1], al[mt], wf[2], wf[3]);
                }
                ldm4(wf, addr + 65536);               // W lo
                #pragma unroll
                for (int mt = 0; mt < 2; mt++) {
                    mma_bf16(acc[mt][np*2],   ah[mt], wf[0], wf[1]);
                    mma_bf16(acc[mt][np*2+1], ah[mt], wf[2], wf[3]);
                }
            }
        }
        __syncthreads();   // all warps done reading A smem -> safe to overwrite

        // ---- fused: epilogue(this tile) + A-build(next tile) ----
        const float* asrc = g_dws + ((size_t)nb * CC + ob * 32) * HWSZ + np0 + px;
        float ring[8];
        if (hasNext) {
            #pragma unroll
            for (int i = 0; i < 8; i++) ring[i] = __ldg(asrc + (size_t)i * HWSZ);
        }

        #pragma unroll
        for (int u = 0; u < 16; u++) {
            int mt = u >> 3, nt = u & 7;
            // epilogue for fragment (mt, nt)
            {
                float* a = acc[mt][nt];
                int ocb = ob * 64 + nt * 8 + 2 * (lane & 3);
                float2 sp = __ldg((const float2*)(g_sp + ocb));
                float v0 = a[0] + sp.x, v1 = a[1] + sp.y;
                float v2 = a[2] + sp.x, v3 = a[3] + sp.y;
                float e0 = __shfl_xor_sync(0xFFFFFFFFu, v0, 1);
                float e1 = __shfl_xor_sync(0xFFFFFFFFu, v1, 1);
                float e2 = __shfl_xor_sync(0xFFFFFFFFu, v2, 1);
                float e3 = __shfl_xor_sync(0xFFFFFFFFu, v3, 1);
                float zi, zf, zo, zg; int rr;
                if ((lane & 1) == 0) { zi = v0; zf = v1; zo = e0; zg = e1; rr = lane >> 2; }
                else                 { zi = e2; zf = e3; zo = v2; zg = v3; rr = (lane >> 2) + 8; }
                int j   = ob * 16 + nt * 2 + ((lane >> 1) & 1);
                int ppx = pb * 32 + mt * 16 + rr;
                size_t plane = ((size_t)b * HID + j) * HWSZ + p0 + ppx;
                float co = __ldg(g_c + plane);
                float gi = gate_f(zi);
                float gf = gate_f(zf);
                float gg = gate_f(zg);
                float go = gate_fast(zo);
                float cv = gf * co + gi * gg;
                float hv = go * tanha(cv);
                g_c[plane] = cv;
                g_h[plane] = hv;
                out[((size_t)(b * TT + t) * HID + j) * HWSZ + p0 + ppx] = hv;
            }
            // A-build slice: consume k-pair (2u, 2u+1), refill ring slots
            if (hasNext) {
                int s0 = (2 * u) & 7, s1 = (2 * u + 1) & 7;
                float a0 = ring[s0], a1 = ring[s1];
                if (2 * u + 8 < 32) {
                    ring[s0] = __ldg(asrc + (size_t)(2 * u + 8) * HWSZ);
                    ring[s1] = __ldg(asrc + (size_t)(2 * u + 9) * HWSZ);
                }
                uint32_t h2;
                asm("cvt.rn.bf16x2.f32 %0, %1, %2;" : "=r"(h2) : "f"(a1), "f"(a0));
                float l0 = a0 - __uint_as_float(h2 << 16);
                float l1 = a1 - __uint_as_float(h2 & 0xFFFF0000u);
                uint32_t l2;
                asm("cvt.rn.bf16x2.f32 %0, %1, %2;" : "=r"(l2) : "f"(l1), "f"(l0));
                uint32_t chunk = (uint32_t)((ob * 4 + (u >> 2)) ^ pxsw);
                uint32_t off = rowb + chunk * 16 + (u & 3) * 4;
                *(uint32_t*)(smem + 131072 + off) = h2;
                *(uint32_t*)(smem + 163840 + off) = l2;
            }
        }
        __syncthreads();   // A(next) fully built before next MMA
    }
}

// -------- launch --------
extern "C" void kernel_launch(void* const* d_in, const int* in_sizes, int n_in,
                              void* d_out, int out_size) {
    const float* x      = (const float*)d_in[0];
    const float* dw_w   = (const float*)d_in[1];
    const float* gamma1 = (const float*)d_in[2];
    const float* beta1  = (const float*)d_in[3];
    const float* mean1  = (const float*)d_in[4];
    const float* var1   = (const float*)d_in[5];
    const float* pw_w   = (const float*)d_in[6];
    const float* gamma2 = (const float*)d_in[7];
    const float* beta2  = (const float*)d_in[8];
    const float* mean2  = (const float*)d_in[9];
    const float* var2   = (const float*)d_in[10];
    float* out = (float*)d_out;

    cudaFuncSetAttribute(pw_kernel, cudaFuncAttributeMaxDynamicSharedMemorySize, 196608);

    init_kernel<<<(BB * HID * HWSZ + 511) / 512, 512>>>();
    prep_kernel<<<1, 256>>>(dw_w, gamma1, beta1, mean1, var1,
                            pw_w, gamma2, beta2, mean2, var2);

    for (int t = 0; t < TT; t++) {
        dw_kernel<<<4096, 256>>>(x, t);
        pw_kernel<<<148, 512, 196608>>>(out, t);
    }
}